// round 1
// baseline (speedup 1.0000x reference)
#include <cuda_runtime.h>
#include <stdint.h>

#define NT 256     // threads per CTA
#define MT 64      // rows (b,d pairs) per CTA  -> 2 full batch elements
#define KC 16      // W chunk rows staged in smem

struct Smem {
    float h[128 * MT];       // h operand, layout [c][m]  (layers 1,2)
    float x[39 * MT];        // x operand, layout [f][m]  (also h for layer 0)
    float w[2][KC * 256];    // double-buffered W chunk
    float rowsum[MT];        // per-row fc_w partial dot accumulator
};

__device__ __forceinline__ void cp16(void* s, const void* g) {
    uint32_t sa = (uint32_t)__cvta_generic_to_shared(s);
    asm volatile("cp.async.cg.shared.global [%0], [%1], 16;" :: "r"(sa), "l"(g));
}

// One cross layer: out = relu(A @ W + b), A[m, f*HP+c] = x[m,f]*h[m,c].
// Epilogue: per-row dot of cols >= colStart with fcw_adj (pre-offset pointer),
// reduced into sm->rowsum; cols < 128 optionally written back as next h.
template<int HP, int KTOT>
__device__ void do_layer(Smem* sm,
                         const float* __restrict__ Wg,
                         const float* __restrict__ bias,
                         const float* __restrict__ fcw_adj,
                         int colStart,
                         const float* __restrict__ hbuf,
                         bool writeH)
{
    const int tid  = threadIdx.x;
    const int warp = tid >> 5;
    const int lane = tid & 31;
    const int r0 = warp * 8;   // 8 rows per warp (uniform across lanes -> smem broadcast)
    const int c0 = lane * 8;   // 8 cols per lane

    float acc[8][8];
#pragma unroll
    for (int i = 0; i < 8; i++)
#pragma unroll
        for (int j = 0; j < 8; j++) acc[i][j] = 0.f;

    const int NCH = (KTOT + KC - 1) / KC;

    // prologue: stage chunk 0
    {
        int rows = KTOT < KC ? KTOT : KC;
        for (int off = tid * 4; off < rows * 256; off += NT * 4)
            cp16(&sm->w[0][off], Wg + off);
        asm volatile("cp.async.commit_group;");
    }

    int f = 0, c = 0;
    for (int ch = 0; ch < NCH; ch++) {
        // prefetch next chunk (possibly empty group)
        {
            int nk0 = (ch + 1) * KC;
            int rows = KTOT - nk0;
            if (rows > KC) rows = KC;
            if (rows > 0) {
                const float* src = Wg + (size_t)nk0 * 256;
                float* dst = sm->w[(ch + 1) & 1];
                for (int off = tid * 4; off < rows * 256; off += NT * 4)
                    cp16(&dst[off], src + off);
            }
            asm volatile("cp.async.commit_group;");
        }
        asm volatile("cp.async.wait_group 1;");   // current chunk resident
        __syncthreads();

        const float* wb = sm->w[ch & 1];
        int kend = KTOT - ch * KC;
        if (kend > KC) kend = KC;

#pragma unroll 4
        for (int kk = 0; kk < kend; kk++) {
            // A fragment: broadcast loads (uniform address across warp)
            const float4 h0 = *(const float4*)&hbuf[c * MT + r0];
            const float4 h1 = *(const float4*)&hbuf[c * MT + r0 + 4];
            const float4 x0 = *(const float4*)&sm->x[f * MT + r0];
            const float4 x1 = *(const float4*)&sm->x[f * MT + r0 + 4];
            float a[8] = { x0.x * h0.x, x0.y * h0.y, x0.z * h0.z, x0.w * h0.w,
                           x1.x * h1.x, x1.y * h1.y, x1.z * h1.z, x1.w * h1.w };
            const float4 w0 = *(const float4*)&wb[kk * 256 + c0];
            const float4 w1 = *(const float4*)&wb[kk * 256 + c0 + 4];
            float w[8] = { w0.x, w0.y, w0.z, w0.w, w1.x, w1.y, w1.z, w1.w };
#pragma unroll
            for (int i = 0; i < 8; i++)
#pragma unroll
                for (int j = 0; j < 8; j++)
                    acc[i][j] += a[i] * w[j];
            if (++c == HP) { c = 0; ++f; }
        }
        __syncthreads();   // safe to overwrite this buffer next iteration
    }

    // epilogue: bias + relu
    float bv[8];
#pragma unroll
    for (int j = 0; j < 8; j++) bv[j] = __ldg(&bias[c0 + j]);
#pragma unroll
    for (int i = 0; i < 8; i++)
#pragma unroll
        for (int j = 0; j < 8; j++) {
            float v = acc[i][j] + bv[j];
            acc[i][j] = v > 0.f ? v : 0.f;
        }

    // per-row fc_w partial dot for the "finals" columns
    float part[8];
#pragma unroll
    for (int i = 0; i < 8; i++) part[i] = 0.f;
    if (c0 >= colStart) {
        float fw[8];
#pragma unroll
        for (int j = 0; j < 8; j++) fw[j] = __ldg(&fcw_adj[c0 + j]);
#pragma unroll
        for (int i = 0; i < 8; i++) {
            float s = 0.f;
#pragma unroll
            for (int j = 0; j < 8; j++) s += acc[i][j] * fw[j];
            part[i] = s;
        }
    }
#pragma unroll
    for (int i = 0; i < 8; i++) {
        float v = part[i];
#pragma unroll
        for (int o = 16; o; o >>= 1) v += __shfl_xor_sync(0xffffffffu, v, o);
        if (lane == 0) sm->rowsum[r0 + i] += v;   // each warp owns its 8 rows
    }

    // write next h (cols 0..127) — all k-loop reads finished at last barrier
    if (writeH && c0 < 128) {
#pragma unroll
        for (int j = 0; j < 8; j++) {
            float4 v0 = make_float4(acc[0][j], acc[1][j], acc[2][j], acc[3][j]);
            float4 v1 = make_float4(acc[4][j], acc[5][j], acc[6][j], acc[7][j]);
            *(float4*)&sm->h[(c0 + j) * MT + r0]     = v0;
            *(float4*)&sm->h[(c0 + j) * MT + r0 + 4] = v1;
        }
    }
    __syncthreads();
}

__global__ void __launch_bounds__(NT, 2)
cin_kernel(const float* __restrict__ x,
           const float* __restrict__ W0, const float* __restrict__ b0,
           const float* __restrict__ W1, const float* __restrict__ b1,
           const float* __restrict__ W2, const float* __restrict__ b2,
           const float* __restrict__ fcw, const float* __restrict__ fcb,
           float* __restrict__ out)
{
    extern __shared__ char smraw[];
    Smem* sm = (Smem*)smraw;
    const int tid = threadIdx.x;
    const int m0 = blockIdx.x * MT;

    if (tid < MT) sm->rowsum[tid] = 0.f;

    // stage x tile: x_t[f][ml] = x[b, f, d],  m = m0+ml, b = m/32, d = m%32
    for (int idx = tid; idx < 39 * MT; idx += NT) {
        int fi = idx >> 6;        // MT = 64
        int ml = idx & 63;
        int m = m0 + ml;
        int b = m >> 5;
        int d = m & 31;
        sm->x[fi * MT + ml] = x[((size_t)b * 39 + fi) * 32 + d];
    }
    __syncthreads();

    // layer 0: h = x (HP=39, K=1521); finals cols 128..255 -> fc_w[0:128]
    do_layer<39, 39 * 39>(sm, W0, b0, fcw - 128, 128, sm->x, true);
    // layer 1: HP=128, K=4992; finals cols 128..255 -> fc_w[128:256]
    do_layer<128, 39 * 128>(sm, W1, b1, fcw, 128, sm->h, true);
    // layer 2: all 256 cols -> fc_w[256:512]
    do_layer<128, 39 * 128>(sm, W2, b2, fcw + 256, 0, sm->h, false);

    // final: each 32-row group (= one batch element) reduces to one scalar
    if (tid < MT) {
        float v = sm->rowsum[tid];
#pragma unroll
        for (int o = 16; o; o >>= 1) v += __shfl_xor_sync(0xffffffffu, v, o);
        if ((tid & 31) == 0)
            out[blockIdx.x * 2 + (tid >> 5)] = v + fcb[0];
    }
}

extern "C" void kernel_launch(void* const* d_in, const int* in_sizes, int n_in,
                              void* d_out, int out_size)
{
    const float* x   = (const float*)d_in[0];
    const float* W0  = (const float*)d_in[1];
    const float* b0  = (const float*)d_in[2];
    const float* W1  = (const float*)d_in[3];
    const float* b1  = (const float*)d_in[4];
    const float* W2  = (const float*)d_in[5];
    const float* b2  = (const float*)d_in[6];
    const float* fcw = (const float*)d_in[7];
    const float* fcb = (const float*)d_in[8];
    float* out = (float*)d_out;

    int B = in_sizes[0] / (39 * 32);     // 1024
    int grid = (B * 32) / MT;            // 512 CTAs, 2 batch elems each

    size_t smem = sizeof(Smem);
    cudaFuncSetAttribute(cin_kernel, cudaFuncAttributeMaxDynamicSharedMemorySize, (int)smem);
    cin_kernel<<<grid, NT, smem>>>(x, W0, b0, W1, b1, W2, b2, fcw, fcb, out);
}

// round 5
// speedup vs baseline: 3.5665x; 3.5665x over previous
#include <cuda_runtime.h>
#include <cuda_bf16.h>
#include <stdint.h>

// ============================ problem constants ============================
#define F_DIM   39
#define NT      256
#define MT      128              // rows (b,d) per CTA
#define NCH0    24               // layer0 k64 chunks (K padded 1521->1536)
#define NCH12   78               // layer1/2 chunks (4992 exact)
#define NCHT    (NCH0 + 2*NCH12) // 180
#define K0_REAL 1521
#define K12     4992
#define CHUNK_ELEMS 16384        // 64 k x 256 n

// weights pre-shuffled into per-lane mma fragment order, bf16 hi/lo
__device__ __align__(256) __nv_bfloat16 g_Bh[(size_t)NCHT * CHUNK_ELEMS];
__device__ __align__(256) __nv_bfloat16 g_Bl[(size_t)NCHT * CHUNK_ELEMS];

// ============================ smem layout (bytes) ==========================
#define B_BUF  65536                     // per buffer: hi 32KB + lo 32KB
#define SM_B   0
#define SM_X   (2*B_BUF)                 // 131072 : x fp32 [128][XS]
#define XS     41
#define SM_H   (SM_X + 128*XS*4)         // 152064 : h fp32 [128][HS]
#define HS     132
#define SM_RS  (SM_H + 128*HS*4)         // 219648 : rowsum[128]
#define SM_TOT (SM_RS + 512)             // 220160

// ============================ helpers ======================================
__device__ __forceinline__ uint32_t s2u(const void* p) {
    uint32_t a;
    asm("{ .reg .u64 t; cvta.to.shared.u64 t, %1; cvt.u32.u64 %0, t; }" : "=r"(a) : "l"(p));
    return a;
}
__device__ __forceinline__ void cp16(uint32_t s, const void* g) {
    asm volatile("cp.async.cg.shared.global [%0], [%1], 16;" :: "r"(s), "l"(g));
}
#define CP_COMMIT() asm volatile("cp.async.commit_group;")
#define CP_WAIT1()  asm volatile("cp.async.wait_group 1;" ::: "memory")

__device__ __forceinline__ void mma_bf16(float* c, const uint32_t* a, uint32_t b0, uint32_t b1) {
    asm volatile("mma.sync.aligned.m16n8k16.row.col.f32.bf16.bf16.f32 "
        "{%0,%1,%2,%3}, {%4,%5,%6,%7}, {%8,%9}, {%0,%1,%2,%3};"
        : "+f"(c[0]), "+f"(c[1]), "+f"(c[2]), "+f"(c[3])
        : "r"(a[0]), "r"(a[1]), "r"(a[2]), "r"(a[3]), "r"(b0), "r"(b1));
}
__device__ __forceinline__ void lds64(uint32_t& r0, uint32_t& r1, uint32_t a) {
    asm volatile("ld.shared.v2.u32 {%0,%1}, [%2];" : "=r"(r0), "=r"(r1) : "r"(a));
}

// ================= weight shuffle kernel (fragment order) ==================
// chunk layout: flat idx o = (((s*32 + nb)*32 + lane)*2 + r)*2 + e
//   n = nb*8 + lane/4,  k_in_chunk = s*16 + (lane%4)*2 + r*8 + e
__global__ void conv_kernel(const float* __restrict__ W, int Kreal, int chunk0) {
    extern __shared__ float ws[];     // [64][257]
    const int lc = blockIdx.x, tid = threadIdx.x;
    for (int i = 0; i < 64; i++) {
        int k = lc * 64 + i;
        ws[i * 257 + tid] = (k < Kreal) ? W[(size_t)k * 256 + tid] : 0.f;
    }
    __syncthreads();
    const size_t base = (size_t)(chunk0 + lc) * CHUNK_ELEMS;
    for (int o = tid; o < CHUNK_ELEMS; o += 256) {
        int e = o & 1, r = (o >> 1) & 1, ln = (o >> 2) & 31;
        int nb = (o >> 7) & 31, s = (o >> 12) & 3;
        int n = nb * 8 + (ln >> 2);
        int kic = s * 16 + (ln & 3) * 2 + r * 8 + e;
        float w = ws[kic * 257 + n];
        __nv_bfloat16 h = __float2bfloat16(w);
        g_Bh[base + o] = h;
        g_Bl[base + o] = __float2bfloat16(w - __bfloat162float(h));
    }
}

// ===================== per-chunk MMA (one k64 chunk) =======================
template<int HP, int HSTR>
__device__ __forceinline__ void chunk_mma(
    const float* __restrict__ xsm, const float* __restrict__ hb,
    uint32_t bbase, int lch, int KR, int lane, int wm, int wn,
    float (&acc)[2][16][4])
{
    const int q2 = (lane & 3) * 2;
    const int rb = wm * 32 + (lane >> 2);
#pragma unroll 1
    for (int s = 0; s < 4; s++) {
        const int kb = lch * 64 + s * 16;
        const int kk[4] = { kb + q2, kb + q2 + 1, kb + q2 + 8, kb + q2 + 9 };
        int ff[4], cc[4];
#pragma unroll
        for (int ki = 0; ki < 4; ki++) { ff[ki] = kk[ki] / HP; cc[ki] = kk[ki] % HP; }

        uint32_t ahi[2][4], alo[2][4];
#pragma unroll
        for (int mt = 0; mt < 2; mt++) {
            float av[2][4];
#pragma unroll
            for (int ki = 0; ki < 4; ki++) {
                const int m_lo = rb + mt * 16, m_hi = m_lo + 8;
                float a0 = xsm[m_lo * XS + ff[ki]] * hb[m_lo * HSTR + cc[ki]];
                float a1 = xsm[m_hi * XS + ff[ki]] * hb[m_hi * HSTR + cc[ki]];
                if (kk[ki] >= KR) { a0 = 0.f; a1 = 0.f; }
                av[0][ki] = a0; av[1][ki] = a1;
            }
#pragma unroll
            for (int h = 0; h < 2; h++) {
                __nv_bfloat162 p01 = __floats2bfloat162_rn(av[h][0], av[h][1]);
                __nv_bfloat162 p23 = __floats2bfloat162_rn(av[h][2], av[h][3]);
                __nv_bfloat162 q01 = __floats2bfloat162_rn(
                    av[h][0] - __low2float(p01), av[h][1] - __high2float(p01));
                __nv_bfloat162 q23 = __floats2bfloat162_rn(
                    av[h][2] - __low2float(p23), av[h][3] - __high2float(p23));
                ahi[mt][h]     = *(uint32_t*)&p01;
                ahi[mt][2 + h] = *(uint32_t*)&p23;
                alo[mt][h]     = *(uint32_t*)&q01;
                alo[mt][2 + h] = *(uint32_t*)&q23;
            }
        }

        const uint32_t rowa = bbase + (((s * 32 + wn * 16) * 32) + lane) * 8;
#pragma unroll
        for (int j = 0; j < 16; j++) {
            uint32_t bh0, bh1, bl0, bl1;
            lds64(bh0, bh1, rowa + j * 256);
            lds64(bl0, bl1, rowa + j * 256 + 32768);
#pragma unroll
            for (int mt = 0; mt < 2; mt++) {
                mma_bf16(acc[mt][j], ahi[mt], bh0, bh1);
                mma_bf16(acc[mt][j], ahi[mt], bl0, bl1);
                mma_bf16(acc[mt][j], alo[mt], bh0, bh1);
            }
        }
    }
}

// ============================ main fused kernel ============================
__global__ void __launch_bounds__(NT, 1)
cin_mma(const float* __restrict__ x,
        const float* __restrict__ b0, const float* __restrict__ b1,
        const float* __restrict__ b2,
        const float* __restrict__ fcw, const float* __restrict__ fcb,
        float* __restrict__ out)
{
    extern __shared__ char sm[];
    const uint32_t smb = s2u(sm);
    float* xsm = (float*)(sm + SM_X);
    float* hsm = (float*)(sm + SM_H);
    float* rowsum = (float*)(sm + SM_RS);

    const int tid = threadIdx.x, wid = tid >> 5, lane = tid & 31;
    const int wm = wid & 3, wn = wid >> 2;
    const int m0 = blockIdx.x * MT;

    if (tid < MT) rowsum[tid] = 0.f;

    // stage x tile: xsm[ml][f] = x[b, f, d];  m = m0+ml, b = m/32, d = m%32
    for (int i = tid; i < F_DIM * MT; i += NT) {
        int f = i >> 7, ml = i & 127, m = m0 + ml;
        xsm[ml * XS + f] = x[((size_t)(m >> 5) * F_DIM + f) * 32 + (m & 31)];
    }

    auto stage = [&](int gch, int q) {
        const __nv_bfloat16* bh = g_Bh + (size_t)gch * CHUNK_ELEMS;
        const __nv_bfloat16* bl = g_Bl + (size_t)gch * CHUNK_ELEMS;
        const uint32_t dst = smb + SM_B + q * B_BUF;
        for (int i = tid; i < 2048; i += NT) {
            cp16(dst + i * 16,         bh + i * 8);
            cp16(dst + 32768 + i * 16, bl + i * 8);
        }
    };

    float acc[2][16][4];
    int gch = 0;
    stage(0, 0);
    CP_COMMIT();

    for (int L = 0; L < 3; L++) {
        const int nch = (L == 0) ? NCH0 : NCH12;
        const int KR  = (L == 0) ? K0_REAL : K12;
#pragma unroll
        for (int mt = 0; mt < 2; mt++)
#pragma unroll
            for (int j = 0; j < 16; j++)
#pragma unroll
                for (int r = 0; r < 4; r++) acc[mt][j][r] = 0.f;

        for (int lch = 0; lch < nch; lch++, gch++) {
            const int q = gch & 1;
            if (gch + 1 < NCHT) stage(gch + 1, q ^ 1);
            CP_COMMIT();
            CP_WAIT1();
            __syncthreads();
            const uint32_t bbase = smb + SM_B + q * B_BUF;
            if (L == 0)
                chunk_mma<F_DIM, XS>(xsm, xsm, bbase, lch, KR, lane, wm, wn, acc);
            else
                chunk_mma<128, HS>(xsm, hsm, bbase, lch, KR, lane, wm, wn, acc);
            __syncthreads();
        }

        // ---- layer epilogue: bias+relu, h feedback, fc_w partial dots ----
        const float* bias = (L == 0) ? b0 : (L == 1) ? b1 : b2;
        const float* fa   = (L == 0) ? (fcw - 128) : (L == 1) ? fcw : (fcw + 256);
        const int cs      = (L < 2) ? 128 : 0;
        const bool wh     = (L < 2);
        float rs[4] = {0.f, 0.f, 0.f, 0.f};
#pragma unroll
        for (int mt = 0; mt < 2; mt++)
#pragma unroll
            for (int j = 0; j < 16; j++)
#pragma unroll
                for (int r = 0; r < 4; r++) {
                    int row = wm * 32 + mt * 16 + (lane >> 2) + ((r >> 1) << 3);
                    int col = wn * 128 + j * 8 + ((lane & 3) << 1) + (r & 1);
                    float v = fmaxf(acc[mt][j][r] + __ldg(&bias[col]), 0.f);
                    if (wh && wn == 0) hsm[row * HS + col] = v;
                    if (col >= cs) rs[mt * 2 + (r >> 1)] += v * __ldg(&fa[col]);
                }
#pragma unroll
        for (int i = 0; i < 4; i++) {
            float v = rs[i];
            v += __shfl_xor_sync(0xffffffffu, v, 1);
            v += __shfl_xor_sync(0xffffffffu, v, 2);
            if ((lane & 3) == 0) {
                int row = wm * 32 + (i >> 1) * 16 + (lane >> 2) + ((i & 1) << 3);
                atomicAdd(&rowsum[row], v);
            }
        }
        __syncthreads();
    }

    // final: each 32-row group (= one batch element) reduces to one scalar
    if (tid < MT) {
        float v = rowsum[tid];
#pragma unroll
        for (int o = 16; o; o >>= 1) v += __shfl_xor_sync(0xffffffffu, v, o);
        if ((tid & 31) == 0) out[blockIdx.x * 4 + wid] = v + fcb[0];
    }
}

// ============================ launch =======================================
extern "C" void kernel_launch(void* const* d_in, const int* in_sizes, int n_in,
                              void* d_out, int out_size)
{
    const float* x   = (const float*)d_in[0];
    const float* W0  = (const float*)d_in[1];
    const float* b0  = (const float*)d_in[2];
    const float* W1  = (const float*)d_in[3];
    const float* b1  = (const float*)d_in[4];
    const float* W2  = (const float*)d_in[5];
    const float* b2  = (const float*)d_in[6];
    const float* fcw = (const float*)d_in[7];
    const float* fcb = (const float*)d_in[8];
    float* out = (float*)d_out;

    // weight shuffle/split (every launch; idempotent, graph-capturable)
    const int conv_smem = 64 * 257 * 4;
    cudaFuncSetAttribute(conv_kernel, cudaFuncAttributeMaxDynamicSharedMemorySize, conv_smem);
    conv_kernel<<<NCH0,  256, conv_smem>>>(W0, K0_REAL, 0);
    conv_kernel<<<NCH12, 256, conv_smem>>>(W1, K12, NCH0);
    conv_kernel<<<NCH12, 256, conv_smem>>>(W2, K12, NCH0 + NCH12);

    int B = in_sizes[0] / (F_DIM * 32);      // 1024
    int grid = (B * 32) / MT;                // 256

    cudaFuncSetAttribute(cin_mma, cudaFuncAttributeMaxDynamicSharedMemorySize, SM_TOT);
    cin_mma<<<grid, NT, SM_TOT>>>(x, b0, b1, b2, fcw, fcb, out);
}